// round 1
// baseline (speedup 1.0000x reference)
#include <cuda_runtime.h>
#include <math.h>

#define NPTS  2048
#define PAIRS 64
#define IVALS 16

// Scratch (static __device__ — no allocations allowed)
__device__ float4   g_y[PAIRS * NPTS];      // transformed source: xyz + |y|^2
__device__ float4   g_x[IVALS * NPTS];      // target prescaled: -2x,-2y,-2z, |x|^2
__device__ unsigned g_colmin[PAIRS * NPTS]; // per-(pair,m) min d2, uint-encoded
__device__ float    g_rowpart[PAIRS * 16];  // per-(pair,split) sum of row mins

// ---------------------------------------------------------------------------
// Kernel 1: transform source points, prescale targets, init colmin scratch
// ---------------------------------------------------------------------------
__global__ void prep_kernel(const float* __restrict__ src,
                            const float* __restrict__ tgt,
                            const float* __restrict__ rot,
                            const float* __restrict__ trn,
                            const float* __restrict__ scl)
{
    int idx = blockIdx.x * blockDim.x + threadIdx.x;
    if (idx >= PAIRS * NPTS) return;
    int pair = idx >> 11;

    float ax = rot[pair * 3 + 0];
    float ay = rot[pair * 3 + 1];
    float az = rot[pair * 3 + 2];
    float sx, cx, sy, cy, sz, cz;
    sincosf(ax, &sx, &cx);
    sincosf(ay, &sy, &cy);
    sincosf(az, &sz, &cz);

    // R = Rx(ax) @ Ry(ay) @ Rz(az)
    float r00 = cy * cz,                 r01 = -cy * sz,                r02 = sy;
    float r10 = cx * sz + sx * sy * cz,  r11 = cx * cz - sx * sy * sz,  r12 = -sx * cy;
    float r20 = sx * sz - cx * sy * cz,  r21 = sx * cz + cx * sy * sz,  r22 = cx * cy;

    float px = src[idx * 3 + 0];
    float py = src[idx * 3 + 1];
    float pz = src[idx * 3 + 2];
    float s  = scl[pair];
    float tx = trn[pair * 3 + 0];
    float ty = trn[pair * 3 + 1];
    float tz = trn[pair * 3 + 2];

    // transformed[k] = s * (sum_d p[d]*R[k][d] + t[k])
    float qx = s * (fmaf(r00, px, fmaf(r01, py, fmaf(r02, pz, tx))));
    float qy = s * (fmaf(r10, px, fmaf(r11, py, fmaf(r12, pz, ty))));
    float qz = s * (fmaf(r20, px, fmaf(r21, py, fmaf(r22, pz, tz))));

    g_y[idx] = make_float4(qx, qy, qz, qx * qx + qy * qy + qz * qz);
    g_colmin[idx] = 0x7F800000u;   // +inf bits

    if (idx < IVALS * NPTS) {
        float bx = tgt[idx * 3 + 0];
        float by = tgt[idx * 3 + 1];
        float bz = tgt[idx * 3 + 2];
        g_x[idx] = make_float4(-2.0f * bx, -2.0f * by, -2.0f * bz,
                               bx * bx + by * by + bz * bz);
    }
}

// ---------------------------------------------------------------------------
// Kernel 2: bidirectional chamfer core.
// Block = (n-split, pair). Block covers 128 target rows x all 2048 cols.
// Thread grid 16(tn) x 16(tm); 8x8 register tile per thread.
//   c(n,m)  = |y_m|^2 - 2 x_n . y_m        (3 chained FMA)
//   d2(n,m) = |x_n|^2 + c(n,m)
// rowmin_n = x2_n + min_m c   (x2 deferred, complete in-block)
// colmin_m = min_n d2         (per-chunk shared reduce + global atomicMin)
// ---------------------------------------------------------------------------
__global__ void __launch_bounds__(256) chamfer_kernel()
{
    const int pair  = blockIdx.y;
    const int nbase = blockIdx.x * 128;
    const int t  = threadIdx.x;
    const int tn = t >> 4;
    const int tm = t & 15;

    __shared__ float4 s_y[128];
    __shared__ float  s_red[16][129];
    __shared__ float  s_sum[8];

    const float4* gx = g_x + (pair & 15) * NPTS + nbase;
    const float4* gy = g_y + pair * NPTS;
    unsigned* cmin = g_colmin + pair * NPTS;

    float4 xf[8];
#pragma unroll
    for (int i = 0; i < 8; i++) xf[i] = gx[tn * 8 + i];

    float rm[8];
#pragma unroll
    for (int i = 0; i < 8; i++) rm[i] = 3.4e38f;

    for (int chunk = 0; chunk < 16; chunk++) {
        const int mbase = chunk * 128;
        __syncthreads();                          // s_y / s_red reuse guard
        if (t < 128) s_y[t] = gy[mbase + t];
        __syncthreads();

        float4 yf[8];
#pragma unroll
        for (int j = 0; j < 8; j++) yf[j] = s_y[tm + 16 * j];

        float cm[8];
#pragma unroll
        for (int j = 0; j < 8; j++) cm[j] = 3.4e38f;

#pragma unroll
        for (int i = 0; i < 8; i++) {
            const float xx = xf[i].x, xy = xf[i].y, xz = xf[i].z, x2 = xf[i].w;
            float rmi = rm[i];
#pragma unroll
            for (int j = 0; j < 8; j++) {
                float c = fmaf(xx, yf[j].x,
                          fmaf(xy, yf[j].y,
                          fmaf(xz, yf[j].z, yf[j].w)));
                rmi   = fminf(rmi, c);
                cm[j] = fminf(cm[j], c + x2);
            }
            rm[i] = rmi;
        }

        // flush col-mins for this chunk: 16-way reduce over tn, then atomicMin
#pragma unroll
        for (int j = 0; j < 8; j++) s_red[tn][tm + 16 * j] = cm[j];
        __syncthreads();
        if (t < 128) {
            float v = s_red[0][t];
#pragma unroll
            for (int k = 1; k < 16; k++) v = fminf(v, s_red[k][t]);
            v = fmaxf(v, 0.0f);   // true d2 >= 0; keeps uint encoding monotone
            atomicMin(&cmin[mbase + t], __float_as_uint(v));
        }
    }

    // finalize row mins: add deferred x2, 16-way reduce over tm, then sum
    __syncthreads();
#pragma unroll
    for (int i = 0; i < 8; i++) s_red[tm][tn * 8 + i] = rm[i] + xf[i].w;
    __syncthreads();

    float total = 0.0f;
    if (t < 128) {
        float v = s_red[0][t];
#pragma unroll
        for (int k = 1; k < 16; k++) v = fminf(v, s_red[k][t]);
        total = v;
    }
#pragma unroll
    for (int off = 16; off > 0; off >>= 1)
        total += __shfl_down_sync(0xffffffffu, total, off);
    if ((t & 31) == 0) s_sum[t >> 5] = total;
    __syncthreads();
    if (t == 0) {
        float acc = s_sum[0] + s_sum[1] + s_sum[2] + s_sum[3];
        g_rowpart[pair * 16 + blockIdx.x] = acc;
    }
}

// ---------------------------------------------------------------------------
// Kernel 3: per-pair means and combine
// ---------------------------------------------------------------------------
__global__ void final_kernel(float* __restrict__ out)
{
    const int pair = blockIdx.x;
    const int t = threadIdx.x;
    float local = 0.0f;
#pragma unroll
    for (int k = 0; k < 8; k++)
        local += __uint_as_float(g_colmin[pair * NPTS + t + 256 * k]);
    if (t < 16) local += g_rowpart[pair * 16 + t];

    __shared__ float sbuf[256];
    sbuf[t] = local;
    __syncthreads();
#pragma unroll
    for (int s = 128; s > 0; s >>= 1) {
        if (t < s) sbuf[t] += sbuf[t + s];
        __syncthreads();
    }
    if (t == 0) out[pair] = sbuf[0] * (1.0f / 2048.0f);
}

// ---------------------------------------------------------------------------
extern "C" void kernel_launch(void* const* d_in, const int* in_sizes, int n_in,
                              void* d_out, int out_size)
{
    const float* src = (const float*)d_in[0];   // [4,16,2048,3]
    const float* tgt = (const float*)d_in[1];   // [16,2048,3]
    const float* rot = (const float*)d_in[2];   // [4,16,3]
    const float* trn = (const float*)d_in[3];   // [4,16,3]
    const float* scl = (const float*)d_in[4];   // [4,16]
    (void)in_sizes; (void)n_in; (void)out_size;

    prep_kernel<<<(PAIRS * NPTS + 255) / 256, 256>>>(src, tgt, rot, trn, scl);
    chamfer_kernel<<<dim3(16, PAIRS), 256>>>();
    final_kernel<<<PAIRS, 256>>>((float*)d_out);
}